// round 6
// baseline (speedup 1.0000x reference)
#include <cuda_runtime.h>

#define NN 50000
#define EE 800000
#define BB 2
#define NB (NN*BB)
#define SCAN_B 1024
#define NBLK ((NN + SCAN_B - 1) / SCAN_B)   // 49

// -------- scratch (__device__ globals; no allocation allowed) --------
__device__ float  g_feat[NN*BB*64];    // [(n*2+b)*64 + h*16+k]
__device__ float  g_el[NN*BB*4];       // [(n*2+b)*4 + h]
__device__ float  g_er[NN*BB*4];
__device__ int    g_deg[NN];
__device__ int    g_off[NN + 1];
__device__ int    g_cursor[NN];
__device__ int    g_bsum[NBLK];
__device__ float2 g_edge[EE];          // dst-sorted: (.x = src bits, .y = w)

// ---------------------------------------------------------------------------
// K1: feat = x @ W_fc.T, plus el/er head dot-products (+ zero g_deg)
// ---------------------------------------------------------------------------
__global__ void k_feat(const float* __restrict__ x, const float* __restrict__ Wfc,
                       const float* __restrict__ al, const float* __restrict__ ar) {
    __shared__ float sW[64][65];
    __shared__ float sx[4][64];
    __shared__ float sal[64], sar[64];
    int tid = threadIdx.x;
    int gid = blockIdx.x * 256 + tid;
    if (gid < NN) g_deg[gid] = 0;          // fused histogram zero
    for (int i = tid; i < 64*64; i += 256) sW[i >> 6][i & 63] = Wfc[i];
    if (tid < 64) { sal[tid] = al[tid]; sar[tid] = ar[tid]; }
    int row = tid >> 6;
    int k   = tid & 63;
    int r = blockIdx.x * 4 + row;           // r = b*N + n
    sx[row][k] = x[r * 64 + k];
    __syncthreads();

    float s = 0.f;
    #pragma unroll
    for (int j = 0; j < 64; j++) s += sx[row][j] * sW[k][j];

    int n = r % NN, b = r / NN;
    int gr = n * 2 + b;
    g_feat[gr * 64 + k] = s;

    float vl = s * sal[k];
    float vr = s * sar[k];
    #pragma unroll
    for (int off = 8; off; off >>= 1) {
        vl += __shfl_down_sync(0xffffffffu, vl, off, 16);
        vr += __shfl_down_sync(0xffffffffu, vr, off, 16);
    }
    if ((k & 15) == 0) {
        int h = k >> 4;
        g_el[gr * 4 + h] = vl;
        g_er[gr * 4 + h] = vr;
    }
}

// ---------------------------------------------------------------------------
// CSR build
// ---------------------------------------------------------------------------
__global__ void k_count(const int* __restrict__ dst) {
    int e = blockIdx.x * blockDim.x + threadIdx.x;
    if (e < EE) atomicAdd(&g_deg[dst[e]], 1);
}

__device__ __forceinline__ int warp_incl_scan(int v, int lane) {
    #pragma unroll
    for (int off = 1; off < 32; off <<= 1) {
        int t = __shfl_up_sync(0xffffffffu, v, off);
        if (lane >= off) v += t;
    }
    return v;
}

__global__ void k_scan1() {                 // warp-shuffle block scan
    __shared__ int wsum[32];
    int tid = threadIdx.x;
    int lane = tid & 31, wid = tid >> 5;
    int i = blockIdx.x * SCAN_B + tid;
    int v = (i < NN) ? g_deg[i] : 0;
    int incl = warp_incl_scan(v, lane);
    if (lane == 31) wsum[wid] = incl;
    __syncthreads();
    if (wid == 0) {
        int s = wsum[lane];
        int si = warp_incl_scan(s, lane);
        wsum[lane] = si - s;                // exclusive warp offsets
    }
    __syncthreads();
    int excl = incl - v + wsum[wid];
    if (i < NN) g_off[i] = excl;
    if (tid == SCAN_B - 1) g_bsum[blockIdx.x] = excl + v;
}

__global__ void k_scan2() {
    __shared__ int s[64];
    int tid = threadIdx.x;
    int v = (tid < NBLK) ? g_bsum[tid] : 0;
    s[tid] = v;
    __syncthreads();
    #pragma unroll
    for (int off = 1; off < 64; off <<= 1) {
        int t = (tid >= off) ? s[tid - off] : 0;
        __syncthreads();
        s[tid] += t;
        __syncthreads();
    }
    if (tid < NBLK) g_bsum[tid] = s[tid] - v;
    if (tid == 0) g_off[NN] = EE;
}

__global__ void k_scan3() {
    int i = blockIdx.x * blockDim.x + threadIdx.x;
    if (i < NN) {
        int o = g_off[i] + g_bsum[i / SCAN_B];
        g_off[i] = o;
        g_cursor[i] = o;
    }
}

__global__ void k_scatter(const int* __restrict__ src, const int* __restrict__ dst,
                          const float* __restrict__ w) {
    int e = blockIdx.x * blockDim.x + threadIdx.x;
    if (e >= EE) return;
    int t = dst[e];
    int pos = atomicAdd(&g_cursor[t], 1);
    g_edge[pos] = make_float2(__int_as_float(src[e]), w[e]);
}

// ---------------------------------------------------------------------------
// K_agg_out: one warp per node, both batches. No max tracking (softmax is
// shift-invariant; scores bounded, fp32 exp safe). Unroll x4, float4 edge
// loads ONLY from even indices (16B alignment); head peel handles odd beg.
// ---------------------------------------------------------------------------
__device__ __forceinline__ float lk(float v) { return (v > 0.f) ? v : 0.1f * v; }

__global__ void __launch_bounds__(256) k_agg_out(
        const float* __restrict__ Wout, const float* __restrict__ bout,
        float* __restrict__ out) {
    __shared__ float sAcc[8][128];
    int warp = threadIdx.x >> 5;
    int lane = threadIdx.x & 31;
    int n = blockIdx.x * 8 + warp;
    if (n >= NN) return;

    int h0sel = lane >> 4;
    float4 e0 = *(const float4*)&g_er[n * 8];
    float4 e1 = *(const float4*)&g_er[n * 8 + 4];
    float er00 = h0sel ? e0.y : e0.x;
    float er01 = h0sel ? e0.w : e0.z;
    float er10 = h0sel ? e1.y : e1.x;
    float er11 = h0sel ? e1.w : e1.z;

    int beg = g_off[n], end = g_off[n + 1];

    float d00 = 0.f, d01 = 0.f, d10 = 0.f, d11 = 0.f;
    float a0 = 0.f, a1 = 0.f, a2 = 0.f, a3 = 0.f;

    int e = beg;
    // head peel: make e even so float4 loads below are 16B-aligned
    if ((e & 1) && e < end) {
        float2 ed = __ldg(&g_edge[e]);
        int   s  = __float_as_int(ed.x);
        float we = ed.y;
        const float4* lp = (const float4*)&g_el[s * 8];
        float4 l0 = __ldg(lp), l1 = __ldg(lp + 1);
        const float* fp = &g_feat[s * 128];
        float f0 = __ldg(fp + lane);
        float f1 = __ldg(fp + 32 + lane);
        float f2 = __ldg(fp + 64 + lane);
        float f3 = __ldg(fp + 96 + lane);
        float x0 = __expf(lk((h0sel ? l0.y : l0.x) + er00) * we);
        float x1 = __expf(lk((h0sel ? l0.w : l0.z) + er01) * we);
        float x2 = __expf(lk((h0sel ? l1.y : l1.x) + er10) * we);
        float x3 = __expf(lk((h0sel ? l1.w : l1.z) + er11) * we);
        d00 += x0; d01 += x1; d10 += x2; d11 += x3;
        a0 += x0 * f0; a1 += x1 * f1; a2 += x2 * f2; a3 += x3 * f3;
        e++;
    }
    for (; e + 3 < end; e += 4) {            // e even: 16B-aligned float4 loads
        float4 eAB = __ldg((const float4*)&g_edge[e]);
        float4 eCD = __ldg((const float4*)&g_edge[e + 2]);
        int sA = __float_as_int(eAB.x), sB = __float_as_int(eAB.z);
        int sC = __float_as_int(eCD.x), sD = __float_as_int(eCD.z);
        float wA = eAB.y, wB = eAB.w, wC = eCD.y, wD = eCD.w;

        const float4* lpA = (const float4*)&g_el[sA * 8];
        const float4* lpB = (const float4*)&g_el[sB * 8];
        const float4* lpC = (const float4*)&g_el[sC * 8];
        const float4* lpD = (const float4*)&g_el[sD * 8];
        float4 lA0 = __ldg(lpA), lA1 = __ldg(lpA + 1);
        float4 lB0 = __ldg(lpB), lB1 = __ldg(lpB + 1);
        float4 lC0 = __ldg(lpC), lC1 = __ldg(lpC + 1);
        float4 lD0 = __ldg(lpD), lD1 = __ldg(lpD + 1);

        const float* fpA = &g_feat[sA * 128];
        const float* fpB = &g_feat[sB * 128];
        const float* fpC = &g_feat[sC * 128];
        const float* fpD = &g_feat[sD * 128];
        float fA0 = __ldg(fpA + lane),      fB0 = __ldg(fpB + lane);
        float fA1 = __ldg(fpA + 32 + lane), fB1 = __ldg(fpB + 32 + lane);
        float fA2 = __ldg(fpA + 64 + lane), fB2 = __ldg(fpB + 64 + lane);
        float fA3 = __ldg(fpA + 96 + lane), fB3 = __ldg(fpB + 96 + lane);
        float fC0 = __ldg(fpC + lane),      fD0 = __ldg(fpD + lane);
        float fC1 = __ldg(fpC + 32 + lane), fD1 = __ldg(fpD + 32 + lane);
        float fC2 = __ldg(fpC + 64 + lane), fD2 = __ldg(fpD + 64 + lane);
        float fC3 = __ldg(fpC + 96 + lane), fD3 = __ldg(fpD + 96 + lane);

        float xA0 = __expf(lk((h0sel ? lA0.y : lA0.x) + er00) * wA);
        float xA1 = __expf(lk((h0sel ? lA0.w : lA0.z) + er01) * wA);
        float xA2 = __expf(lk((h0sel ? lA1.y : lA1.x) + er10) * wA);
        float xA3 = __expf(lk((h0sel ? lA1.w : lA1.z) + er11) * wA);
        float xB0 = __expf(lk((h0sel ? lB0.y : lB0.x) + er00) * wB);
        float xB1 = __expf(lk((h0sel ? lB0.w : lB0.z) + er01) * wB);
        float xB2 = __expf(lk((h0sel ? lB1.y : lB1.x) + er10) * wB);
        float xB3 = __expf(lk((h0sel ? lB1.w : lB1.z) + er11) * wB);
        float xC0 = __expf(lk((h0sel ? lC0.y : lC0.x) + er00) * wC);
        float xC1 = __expf(lk((h0sel ? lC0.w : lC0.z) + er01) * wC);
        float xC2 = __expf(lk((h0sel ? lC1.y : lC1.x) + er10) * wC);
        float xC3 = __expf(lk((h0sel ? lC1.w : lC1.z) + er11) * wC);
        float xD0 = __expf(lk((h0sel ? lD0.y : lD0.x) + er00) * wD);
        float xD1 = __expf(lk((h0sel ? lD0.w : lD0.z) + er01) * wD);
        float xD2 = __expf(lk((h0sel ? lD1.y : lD1.x) + er10) * wD);
        float xD3 = __expf(lk((h0sel ? lD1.w : lD1.z) + er11) * wD);

        d00 += (xA0 + xB0) + (xC0 + xD0);
        d01 += (xA1 + xB1) + (xC1 + xD1);
        d10 += (xA2 + xB2) + (xC2 + xD2);
        d11 += (xA3 + xB3) + (xC3 + xD3);
        a0 += xA0 * fA0 + xB0 * fB0 + xC0 * fC0 + xD0 * fD0;
        a1 += xA1 * fA1 + xB1 * fB1 + xC1 * fC1 + xD1 * fD1;
        a2 += xA2 * fA2 + xB2 * fB2 + xC2 * fC2 + xD2 * fD2;
        a3 += xA3 * fA3 + xB3 * fB3 + xC3 * fC3 + xD3 * fD3;
    }
    for (; e < end; e++) {                   // tail (0..3 edges)
        float2 ed = __ldg(&g_edge[e]);
        int   s  = __float_as_int(ed.x);
        float we = ed.y;
        const float4* lp = (const float4*)&g_el[s * 8];
        float4 l0 = __ldg(lp), l1 = __ldg(lp + 1);
        const float* fp = &g_feat[s * 128];
        float f0 = __ldg(fp + lane);
        float f1 = __ldg(fp + 32 + lane);
        float f2 = __ldg(fp + 64 + lane);
        float f3 = __ldg(fp + 96 + lane);
        float x0 = __expf(lk((h0sel ? l0.y : l0.x) + er00) * we);
        float x1 = __expf(lk((h0sel ? l0.w : l0.z) + er01) * we);
        float x2 = __expf(lk((h0sel ? l1.y : l1.x) + er10) * we);
        float x3 = __expf(lk((h0sel ? l1.w : l1.z) + er11) * we);
        d00 += x0; d01 += x1; d10 += x2; d11 += x3;
        a0 += x0 * f0; a1 += x1 * f1; a2 += x2 * f2; a3 += x3 * f3;
    }

    float i00 = (d00 > 0.f) ? 1.f / d00 : 0.f;
    float i01 = (d01 > 0.f) ? 1.f / d01 : 0.f;
    float i10 = (d10 > 0.f) ? 1.f / d10 : 0.f;
    float i11 = (d11 > 0.f) ? 1.f / d11 : 0.f;
    sAcc[warp][lane]      = a0 * i00;
    sAcc[warp][32 + lane] = a1 * i01;
    sAcc[warp][64 + lane] = a2 * i10;
    sAcc[warp][96 + lane] = a3 * i11;
    __syncwarp();

    float4 wA[4], wB[4];
    #pragma unroll
    for (int q = 0; q < 4; q++) {
        wA[q] = __ldg(&((const float4*)&Wout[lane * 16])[q]);
        wB[q] = __ldg(&((const float4*)&Wout[(lane + 32) * 16])[q]);
    }
    float bias0 = __ldg(&bout[lane]), bias1 = __ldg(&bout[lane + 32]);

    #pragma unroll
    for (int b = 0; b < 2; b++) {
        #pragma unroll
        for (int h = 0; h < 4; h++) {
            const float4* ap = (const float4*)&sAcc[warp][b * 64 + h * 16];
            float acc0 = bias0, acc1 = bias1;
            #pragma unroll
            for (int q = 0; q < 4; q++) {
                float4 av = ap[q];
                acc0 += av.x * wA[q].x + av.y * wA[q].y + av.z * wA[q].z + av.w * wA[q].w;
                acc1 += av.x * wB[q].x + av.y * wB[q].y + av.z * wB[q].z + av.w * wB[q].w;
            }
            float* op = &out[((b * NN + n) * 4 + h) * 64];
            op[lane]      = acc0;
            op[lane + 32] = acc1;
        }
    }
}

// ---------------------------------------------------------------------------
// inputs: vt, x, w, src, dst, W_fc, attn_l, attn_r, W_out, b_out
// ---------------------------------------------------------------------------
extern "C" void kernel_launch(void* const* d_in, const int* in_sizes, int n_in,
                              void* d_out, int out_size) {
    const float* x    = (const float*)d_in[1];
    const float* w    = (const float*)d_in[2];
    const int*   src  = (const int*)  d_in[3];
    const int*   dst  = (const int*)  d_in[4];
    const float* Wfc  = (const float*)d_in[5];
    const float* al   = (const float*)d_in[6];
    const float* ar   = (const float*)d_in[7];
    const float* Wout = (const float*)d_in[8];
    const float* bout = (const float*)d_in[9];
    float* out = (float*)d_out;

    k_feat<<<NB / 4, 256>>>(x, Wfc, al, ar);
    k_count<<<(EE + 255) / 256, 256>>>(dst);
    k_scan1<<<NBLK, SCAN_B>>>();
    k_scan2<<<1, 64>>>();
    k_scan3<<<(NN + 255) / 256, 256>>>();
    k_scatter<<<(EE + 255) / 256, 256>>>(src, dst, w);
    k_agg_out<<<(NN + 7) / 8, 256>>>(Wout, bout, out);
}

// round 7
// speedup vs baseline: 1.1164x; 1.1164x over previous
#include <cuda_runtime.h>

#define NN 50000
#define EE 800000
#define BB 2
#define NB (NN*BB)
#define SCAN_B 1024
#define NBLK ((NN + SCAN_B - 1) / SCAN_B)   // 49

// -------- scratch (__device__ globals; zero-initialized at module load) ----
__device__ float  g_feat[NN*BB*64];    // [(n*2+b)*64 + h*16+k]
__device__ float  g_el[NN*BB*4];       // [(n*2+b)*4 + h]
__device__ float  g_er[NN*BB*4];
__device__ int    g_deg[NN];           // INVARIANT: zero at entry of each call
__device__ int    g_off[NN + 1];
__device__ int    g_cursor[NN];
__device__ unsigned long long g_tile[NBLK];  // lookback state: zero at entry
__device__ float2 g_edge[EE];          // dst-sorted: (.x = src bits, .y = w)

// ---------------------------------------------------------------------------
// K1: feat = x @ W_fc.T + el/er head dots + degree histogram (fused count)
// ---------------------------------------------------------------------------
__global__ void k_featcnt(const float* __restrict__ x, const float* __restrict__ Wfc,
                          const float* __restrict__ al, const float* __restrict__ ar,
                          const int* __restrict__ dst) {
    __shared__ float sW[64][65];
    __shared__ float sx[4][64];
    __shared__ float sal[64], sar[64];
    int tid = threadIdx.x;
    int gid = blockIdx.x * 256 + tid;
    if (gid < EE) atomicAdd(&g_deg[dst[gid]], 1);   // fused histogram
    for (int i = tid; i < 64*64; i += 256) sW[i >> 6][i & 63] = Wfc[i];
    if (tid < 64) { sal[tid] = al[tid]; sar[tid] = ar[tid]; }
    int row = tid >> 6;
    int k   = tid & 63;
    int r = blockIdx.x * 4 + row;           // r = b*N + n
    sx[row][k] = x[r * 64 + k];
    __syncthreads();

    float s = 0.f;
    #pragma unroll
    for (int j = 0; j < 64; j++) s += sx[row][j] * sW[k][j];

    int n = r % NN, b = r / NN;
    int gr = n * 2 + b;
    g_feat[gr * 64 + k] = s;

    float vl = s * sal[k];
    float vr = s * sar[k];
    #pragma unroll
    for (int off = 8; off; off >>= 1) {
        vl += __shfl_down_sync(0xffffffffu, vl, off, 16);
        vr += __shfl_down_sync(0xffffffffu, vr, off, 16);
    }
    if ((k & 15) == 0) {
        int h = k >> 4;
        g_el[gr * 4 + h] = vl;
        g_er[gr * 4 + h] = vr;
    }
}

// ---------------------------------------------------------------------------
// K2: single-pass exclusive scan (decoupled lookback, 49 tiles all resident)
// g_tile word: [63:62]=status (0 invalid, 1 aggregate, 2 prefix), [31:0]=value
// ---------------------------------------------------------------------------
__device__ __forceinline__ int warp_incl_scan(int v, int lane) {
    #pragma unroll
    for (int off = 1; off < 32; off <<= 1) {
        int t = __shfl_up_sync(0xffffffffu, v, off);
        if (lane >= off) v += t;
    }
    return v;
}

__global__ void k_scan() {
    __shared__ int wsum[32];
    __shared__ int s_total;
    __shared__ int s_pref;
    int tid = threadIdx.x, lane = tid & 31, wid = tid >> 5;
    int i = blockIdx.x * SCAN_B + tid;
    int v = (i < NN) ? g_deg[i] : 0;
    int incl = warp_incl_scan(v, lane);
    if (lane == 31) wsum[wid] = incl;
    __syncthreads();
    if (wid == 0) {
        int s = wsum[lane];
        int si = warp_incl_scan(s, lane);
        wsum[lane] = si - s;
        if (lane == 31) s_total = si;
    }
    __syncthreads();
    int excl = incl - v + wsum[wid];
    if (tid == 0) {
        int total = s_total;
        int bx = blockIdx.x;
        if (bx == 0) {
            s_pref = 0;
            *(volatile unsigned long long*)&g_tile[0] =
                (2ULL << 62) | (unsigned int)total;
            g_off[NN] = EE;
        } else {
            // publish aggregate first so successors can proceed
            *(volatile unsigned long long*)&g_tile[bx] =
                (1ULL << 62) | (unsigned int)total;
            int pref = 0;
            int j = bx - 1;
            while (1) {
                unsigned long long t = *(volatile unsigned long long*)&g_tile[j];
                unsigned int st = (unsigned int)(t >> 62);
                if (st == 0) continue;
                pref += (int)(t & 0xffffffffULL);
                if (st == 2) break;
                j--;
            }
            s_pref = pref;
            *(volatile unsigned long long*)&g_tile[bx] =
                (2ULL << 62) | (unsigned int)(pref + total);
        }
    }
    __syncthreads();
    int off = excl + s_pref;
    if (i < NN) { g_off[i] = off; g_cursor[i] = off; }
}

// ---------------------------------------------------------------------------
// K3: scatter edges into dst-sorted order
// ---------------------------------------------------------------------------
__global__ void k_scatter(const int* __restrict__ src, const int* __restrict__ dst,
                          const float* __restrict__ w) {
    int e = blockIdx.x * blockDim.x + threadIdx.x;
    if (e >= EE) return;
    int t = dst[e];
    int pos = atomicAdd(&g_cursor[t], 1);
    g_edge[pos] = make_float2(__int_as_float(src[e]), w[e]);
}

// ---------------------------------------------------------------------------
// K4: one warp per node, both batches. No max tracking (shift-invariant
// softmax; scores bounded). Unroll x2 (moderate regs, MLP ~13). Also resets
// g_deg / g_tile for the NEXT call (cross-call invariant).
// ---------------------------------------------------------------------------
__device__ __forceinline__ float lk(float v) { return (v > 0.f) ? v : 0.1f * v; }

__global__ void __launch_bounds__(256) k_agg_out(
        const float* __restrict__ Wout, const float* __restrict__ bout,
        float* __restrict__ out) {
    __shared__ float sAcc[8][128];
    int tid = threadIdx.x;
    int gid = blockIdx.x * 256 + tid;
    if (gid < NN) g_deg[gid] = 0;                    // reset for next call
    if (gid < NBLK) g_tile[gid] = 0ULL;

    int warp = tid >> 5;
    int lane = tid & 31;
    int n = blockIdx.x * 8 + warp;
    if (n >= NN) return;

    int h0sel = lane >> 4;
    float4 e0 = *(const float4*)&g_er[n * 8];
    float4 e1 = *(const float4*)&g_er[n * 8 + 4];
    float er00 = h0sel ? e0.y : e0.x;
    float er01 = h0sel ? e0.w : e0.z;
    float er10 = h0sel ? e1.y : e1.x;
    float er11 = h0sel ? e1.w : e1.z;

    int beg = g_off[n], end = g_off[n + 1];

    float d00 = 0.f, d01 = 0.f, d10 = 0.f, d11 = 0.f;
    float a0 = 0.f, a1 = 0.f, a2 = 0.f, a3 = 0.f;

    int e = beg;
    // head peel: make e even so the float4 edge load is 16B-aligned
    if ((e & 1) && e < end) {
        float2 ed = __ldg(&g_edge[e]);
        int   s  = __float_as_int(ed.x);
        float we = ed.y;
        const float4* lp = (const float4*)&g_el[s * 8];
        float4 l0 = __ldg(lp), l1 = __ldg(lp + 1);
        const float* fp = &g_feat[s * 128];
        float f0 = __ldg(fp + lane);
        float f1 = __ldg(fp + 32 + lane);
        float f2 = __ldg(fp + 64 + lane);
        float f3 = __ldg(fp + 96 + lane);
        float x0 = __expf(lk((h0sel ? l0.y : l0.x) + er00) * we);
        float x1 = __expf(lk((h0sel ? l0.w : l0.z) + er01) * we);
        float x2 = __expf(lk((h0sel ? l1.y : l1.x) + er10) * we);
        float x3 = __expf(lk((h0sel ? l1.w : l1.z) + er11) * we);
        d00 += x0; d01 += x1; d10 += x2; d11 += x3;
        a0 += x0 * f0; a1 += x1 * f1; a2 += x2 * f2; a3 += x3 * f3;
        e++;
    }
    for (; e + 1 < end; e += 2) {            // e even: aligned float4 edge load
        float4 eAB = __ldg((const float4*)&g_edge[e]);
        int sA = __float_as_int(eAB.x), sB = __float_as_int(eAB.z);
        float wA = eAB.y, wB = eAB.w;

        const float4* lpA = (const float4*)&g_el[sA * 8];
        const float4* lpB = (const float4*)&g_el[sB * 8];
        float4 lA0 = __ldg(lpA), lA1 = __ldg(lpA + 1);
        float4 lB0 = __ldg(lpB), lB1 = __ldg(lpB + 1);

        const float* fpA = &g_feat[sA * 128];
        const float* fpB = &g_feat[sB * 128];
        float fA0 = __ldg(fpA + lane),      fB0 = __ldg(fpB + lane);
        float fA1 = __ldg(fpA + 32 + lane), fB1 = __ldg(fpB + 32 + lane);
        float fA2 = __ldg(fpA + 64 + lane), fB2 = __ldg(fpB + 64 + lane);
        float fA3 = __ldg(fpA + 96 + lane), fB3 = __ldg(fpB + 96 + lane);

        float xA0 = __expf(lk((h0sel ? lA0.y : lA0.x) + er00) * wA);
        float xA1 = __expf(lk((h0sel ? lA0.w : lA0.z) + er01) * wA);
        float xA2 = __expf(lk((h0sel ? lA1.y : lA1.x) + er10) * wA);
        float xA3 = __expf(lk((h0sel ? lA1.w : lA1.z) + er11) * wA);
        float xB0 = __expf(lk((h0sel ? lB0.y : lB0.x) + er00) * wB);
        float xB1 = __expf(lk((h0sel ? lB0.w : lB0.z) + er01) * wB);
        float xB2 = __expf(lk((h0sel ? lB1.y : lB1.x) + er10) * wB);
        float xB3 = __expf(lk((h0sel ? lB1.w : lB1.z) + er11) * wB);

        d00 += xA0 + xB0;  d01 += xA1 + xB1;
        d10 += xA2 + xB2;  d11 += xA3 + xB3;
        a0 += xA0 * fA0 + xB0 * fB0;
        a1 += xA1 * fA1 + xB1 * fB1;
        a2 += xA2 * fA2 + xB2 * fB2;
        a3 += xA3 * fA3 + xB3 * fB3;
    }
    if (e < end) {                           // tail edge
        float2 ed = __ldg(&g_edge[e]);
        int   s  = __float_as_int(ed.x);
        float we = ed.y;
        const float4* lp = (const float4*)&g_el[s * 8];
        float4 l0 = __ldg(lp), l1 = __ldg(lp + 1);
        const float* fp = &g_feat[s * 128];
        float f0 = __ldg(fp + lane);
        float f1 = __ldg(fp + 32 + lane);
        float f2 = __ldg(fp + 64 + lane);
        float f3 = __ldg(fp + 96 + lane);
        float x0 = __expf(lk((h0sel ? l0.y : l0.x) + er00) * we);
        float x1 = __expf(lk((h0sel ? l0.w : l0.z) + er01) * we);
        float x2 = __expf(lk((h0sel ? l1.y : l1.x) + er10) * we);
        float x3 = __expf(lk((h0sel ? l1.w : l1.z) + er11) * we);
        d00 += x0; d01 += x1; d10 += x2; d11 += x3;
        a0 += x0 * f0; a1 += x1 * f1; a2 += x2 * f2; a3 += x3 * f3;
    }

    float i00 = (d00 > 0.f) ? 1.f / d00 : 0.f;
    float i01 = (d01 > 0.f) ? 1.f / d01 : 0.f;
    float i10 = (d10 > 0.f) ? 1.f / d10 : 0.f;
    float i11 = (d11 > 0.f) ? 1.f / d11 : 0.f;
    sAcc[warp][lane]      = a0 * i00;
    sAcc[warp][32 + lane] = a1 * i01;
    sAcc[warp][64 + lane] = a2 * i10;
    sAcc[warp][96 + lane] = a3 * i11;
    __syncwarp();

    float4 wA[4], wB[4];
    #pragma unroll
    for (int q = 0; q < 4; q++) {
        wA[q] = __ldg(&((const float4*)&Wout[lane * 16])[q]);
        wB[q] = __ldg(&((const float4*)&Wout[(lane + 32) * 16])[q]);
    }
    float bias0 = __ldg(&bout[lane]), bias1 = __ldg(&bout[lane + 32]);

    #pragma unroll
    for (int b = 0; b < 2; b++) {
        #pragma unroll
        for (int h = 0; h < 4; h++) {
            const float4* ap = (const float4*)&sAcc[warp][b * 64 + h * 16];
            float acc0 = bias0, acc1 = bias1;
            #pragma unroll
            for (int q = 0; q < 4; q++) {
                float4 av = ap[q];
                acc0 += av.x * wA[q].x + av.y * wA[q].y + av.z * wA[q].z + av.w * wA[q].w;
                acc1 += av.x * wB[q].x + av.y * wB[q].y + av.z * wB[q].z + av.w * wB[q].w;
            }
            float* op = &out[((b * NN + n) * 4 + h) * 64];
            op[lane]      = acc0;
            op[lane + 32] = acc1;
        }
    }
}

// ---------------------------------------------------------------------------
// inputs: vt, x, w, src, dst, W_fc, attn_l, attn_r, W_out, b_out
// ---------------------------------------------------------------------------
extern "C" void kernel_launch(void* const* d_in, const int* in_sizes, int n_in,
                              void* d_out, int out_size) {
    const float* x    = (const float*)d_in[1];
    const float* w    = (const float*)d_in[2];
    const int*   src  = (const int*)  d_in[3];
    const int*   dst  = (const int*)  d_in[4];
    const float* Wfc  = (const float*)d_in[5];
    const float* al   = (const float*)d_in[6];
    const float* ar   = (const float*)d_in[7];
    const float* Wout = (const float*)d_in[8];
    const float* bout = (const float*)d_in[9];
    float* out = (float*)d_out;

    k_featcnt<<<NB / 4, 256>>>(x, Wfc, al, ar, dst);
    k_scan<<<NBLK, SCAN_B>>>();
    k_scatter<<<(EE + 255) / 256, 256>>>(src, dst, w);
    k_agg_out<<<(NN + 7) / 8, 256>>>(Wout, bout, out);
}

// round 8
// speedup vs baseline: 1.8970x; 1.6991x over previous
#include <cuda_runtime.h>

#define NN 50000
#define EE 800000
#define BB 2
#define NB (NN*BB)
#define SCAN_B 1024
#define NBLK ((NN + SCAN_B - 1) / SCAN_B)   // 49

// -------- scratch (__device__ globals; zero-initialized at module load) ----
__device__ float  g_feat[NN*BB*64];    // [(n*2+b)*64 + h*16+k]
__device__ float  g_el[NN*BB*4];       // [(n*2+b)*4 + h]
__device__ float  g_er[NN*BB*4];
__device__ int    g_deg[NN];           // INVARIANT: zero at entry of each call
__device__ int    g_off[NN + 1];
__device__ int    g_cursor[NN];
__device__ unsigned long long g_tile[NBLK];  // lookback state: zero at entry
__device__ float2 g_edge[EE];          // dst-sorted: (.x = src bits, .y = w)

// ---------------------------------------------------------------------------
// K1: feat = x @ W_fc.T + el/er head dots + degree histogram.
// 32 rows/block, thread = (rowPair, k4): 2 rows x 4 outputs via float4 LDS.
// sWT[j*68+k] = W[k][j] (transposed, padded 68 for aligned float4 reads).
// grid*block == EE exactly -> unguarded histogram.
// ---------------------------------------------------------------------------
__global__ void __launch_bounds__(256) k_featcnt(
        const float* __restrict__ x, const float* __restrict__ Wfc,
        const float* __restrict__ al, const float* __restrict__ ar,
        const int* __restrict__ dst) {
    __shared__ float sWT[64 * 68];
    __shared__ float4 sx4[32][16];
    int tid = threadIdx.x;
    int gid = blockIdx.x * 256 + tid;          // in [0, EE) exactly
    atomicAdd(&g_deg[dst[gid]], 1);

    for (int i = tid; i < 4096; i += 256) {    // coalesced W read
        int k = i >> 6, j = i & 63;
        sWT[j * 68 + k] = Wfc[i];
    }
    int k4   = tid & 15;
    int rowh = tid >> 4;
    int r0 = blockIdx.x * 32 + rowh * 2;       // r = b*N + n
    sx4[rowh * 2 + 0][k4] = ((const float4*)x)[(r0 + 0) * 16 + k4];
    sx4[rowh * 2 + 1][k4] = ((const float4*)x)[(r0 + 1) * 16 + k4];
    __syncthreads();

    float4 s0 = make_float4(0.f, 0.f, 0.f, 0.f);
    float4 s1 = make_float4(0.f, 0.f, 0.f, 0.f);
    #pragma unroll
    for (int j4 = 0; j4 < 16; j4++) {
        float4 x0 = sx4[rowh * 2][j4];
        float4 x1 = sx4[rowh * 2 + 1][j4];
        float4 w0 = *(const float4*)&sWT[(4 * j4 + 0) * 68 + 4 * k4];
        float4 w1 = *(const float4*)&sWT[(4 * j4 + 1) * 68 + 4 * k4];
        float4 w2 = *(const float4*)&sWT[(4 * j4 + 2) * 68 + 4 * k4];
        float4 w3 = *(const float4*)&sWT[(4 * j4 + 3) * 68 + 4 * k4];
        s0.x += x0.x*w0.x + x0.y*w1.x + x0.z*w2.x + x0.w*w3.x;
        s0.y += x0.x*w0.y + x0.y*w1.y + x0.z*w2.y + x0.w*w3.y;
        s0.z += x0.x*w0.z + x0.y*w1.z + x0.z*w2.z + x0.w*w3.z;
        s0.w += x0.x*w0.w + x0.y*w1.w + x0.z*w2.w + x0.w*w3.w;
        s1.x += x1.x*w0.x + x1.y*w1.x + x1.z*w2.x + x1.w*w3.x;
        s1.y += x1.x*w0.y + x1.y*w1.y + x1.z*w2.y + x1.w*w3.y;
        s1.z += x1.x*w0.z + x1.y*w1.z + x1.z*w2.z + x1.w*w3.z;
        s1.w += x1.x*w0.w + x1.y*w1.w + x1.z*w2.w + x1.w*w3.w;
    }

    int n0 = r0 % NN, b0 = r0 / NN;
    int r1 = r0 + 1;
    int n1 = r1 % NN, b1 = r1 / NN;
    int gr0 = n0 * 2 + b0, gr1 = n1 * 2 + b1;
    ((float4*)&g_feat[gr0 * 64])[k4] = s0;
    ((float4*)&g_feat[gr1 * 64])[k4] = s1;

    float4 al4 = __ldg(&((const float4*)al)[k4]);
    float4 ar4 = __ldg(&((const float4*)ar)[k4]);
    float pl0 = s0.x*al4.x + s0.y*al4.y + s0.z*al4.z + s0.w*al4.w;
    float pr0 = s0.x*ar4.x + s0.y*ar4.y + s0.z*ar4.z + s0.w*ar4.w;
    float pl1 = s1.x*al4.x + s1.y*al4.y + s1.z*al4.z + s1.w*al4.w;
    float pr1 = s1.x*ar4.x + s1.y*ar4.y + s1.z*ar4.z + s1.w*ar4.w;
    pl0 += __shfl_down_sync(0xffffffffu, pl0, 2);
    pl0 += __shfl_down_sync(0xffffffffu, pl0, 1);
    pr0 += __shfl_down_sync(0xffffffffu, pr0, 2);
    pr0 += __shfl_down_sync(0xffffffffu, pr0, 1);
    pl1 += __shfl_down_sync(0xffffffffu, pl1, 2);
    pl1 += __shfl_down_sync(0xffffffffu, pl1, 1);
    pr1 += __shfl_down_sync(0xffffffffu, pr1, 2);
    pr1 += __shfl_down_sync(0xffffffffu, pr1, 1);
    if ((tid & 3) == 0) {
        int h = k4 >> 2;
        g_el[gr0 * 4 + h] = pl0;  g_er[gr0 * 4 + h] = pr0;
        g_el[gr1 * 4 + h] = pl1;  g_er[gr1 * 4 + h] = pr1;
    }
}

// ---------------------------------------------------------------------------
// K2: single-pass exclusive scan (decoupled lookback, 49 tiles all resident)
// ---------------------------------------------------------------------------
__device__ __forceinline__ int warp_incl_scan(int v, int lane) {
    #pragma unroll
    for (int off = 1; off < 32; off <<= 1) {
        int t = __shfl_up_sync(0xffffffffu, v, off);
        if (lane >= off) v += t;
    }
    return v;
}

__global__ void k_scan() {
    __shared__ int wsum[32];
    __shared__ int s_total;
    __shared__ int s_pref;
    int tid = threadIdx.x, lane = tid & 31, wid = tid >> 5;
    int i = blockIdx.x * SCAN_B + tid;
    int v = (i < NN) ? g_deg[i] : 0;
    int incl = warp_incl_scan(v, lane);
    if (lane == 31) wsum[wid] = incl;
    __syncthreads();
    if (wid == 0) {
        int s = wsum[lane];
        int si = warp_incl_scan(s, lane);
        wsum[lane] = si - s;
        if (lane == 31) s_total = si;
    }
    __syncthreads();
    int excl = incl - v + wsum[wid];
    if (tid == 0) {
        int total = s_total;
        int bx = blockIdx.x;
        if (bx == 0) {
            s_pref = 0;
            *(volatile unsigned long long*)&g_tile[0] =
                (2ULL << 62) | (unsigned int)total;
            g_off[NN] = EE;
        } else {
            *(volatile unsigned long long*)&g_tile[bx] =
                (1ULL << 62) | (unsigned int)total;
            int pref = 0;
            int j = bx - 1;
            while (1) {
                unsigned long long t = *(volatile unsigned long long*)&g_tile[j];
                unsigned int st = (unsigned int)(t >> 62);
                if (st == 0) continue;
                pref += (int)(t & 0xffffffffULL);
                if (st == 2) break;
                j--;
            }
            s_pref = pref;
            *(volatile unsigned long long*)&g_tile[bx] =
                (2ULL << 62) | (unsigned int)(pref + total);
        }
    }
    __syncthreads();
    int off = excl + s_pref;
    if (i < NN) { g_off[i] = off; g_cursor[i] = off; }
}

// ---------------------------------------------------------------------------
// K3: scatter edges into dst-sorted order
// ---------------------------------------------------------------------------
__global__ void k_scatter(const int* __restrict__ src, const int* __restrict__ dst,
                          const float* __restrict__ w) {
    int e = blockIdx.x * blockDim.x + threadIdx.x;
    if (e >= EE) return;
    int t = dst[e];
    int pos = atomicAdd(&g_cursor[t], 1);
    g_edge[pos] = make_float2(__int_as_float(src[e]), w[e]);
}

// ---------------------------------------------------------------------------
// K4: one warp per node. Lane owns float4 j=4*lane..4*lane+3 of the 128-wide
// (b,h,k) vector => ONE (b,h) score/exp per lane per edge, one LDG.128 feat.
// No max tracking (shift-invariant softmax; scores bounded). Unroll x2.
// Also resets g_deg / g_tile for the NEXT call.
// ---------------------------------------------------------------------------
__device__ __forceinline__ float lk(float v) { return (v > 0.f) ? v : 0.1f * v; }

__global__ void __launch_bounds__(256) k_agg_out(
        const float* __restrict__ Wout, const float* __restrict__ bout,
        float* __restrict__ out) {
    __shared__ float sAcc[8][128];
    int tid = threadIdx.x;
    int gid = blockIdx.x * 256 + tid;
    if (gid < NN) g_deg[gid] = 0;                    // reset for next call
    if (gid < NBLK) g_tile[gid] = 0ULL;

    int warp = tid >> 5;
    int lane = tid & 31;
    int n = blockIdx.x * 8 + warp;
    if (n >= NN) return;

    int q = lane >> 2;                  // (b*4 + h) for this lane
    float er_l = g_er[n * 8 + q];

    int beg = g_off[n], end = g_off[n + 1];

    float4 a = make_float4(0.f, 0.f, 0.f, 0.f);
    float  d = 0.f;

    int e = beg;
    if ((e & 1) && e < end) {            // head peel for 16B edge alignment
        float2 ed = __ldg(&g_edge[e]);
        int   s  = __float_as_int(ed.x);
        float we = ed.y;
        float xs = __expf(lk(__ldg(&g_el[s * 8 + q]) + er_l) * we);
        float4 f = __ldg((const float4*)&g_feat[s * 128 + 4 * lane]);
        d += xs;
        a.x += xs * f.x; a.y += xs * f.y; a.z += xs * f.z; a.w += xs * f.w;
        e++;
    }
    for (; e + 1 < end; e += 2) {        // e even: aligned float4 edge load
        float4 eAB = __ldg((const float4*)&g_edge[e]);
        int sA = __float_as_int(eAB.x), sB = __float_as_int(eAB.z);
        float wA = eAB.y, wB = eAB.w;

        float elA = __ldg(&g_el[sA * 8 + q]);
        float elB = __ldg(&g_el[sB * 8 + q]);
        float4 fA = __ldg((const float4*)&g_feat[sA * 128 + 4 * lane]);
        float4 fB = __ldg((const float4*)&g_feat[sB * 128 + 4 * lane]);

        float xA = __expf(lk(elA + er_l) * wA);
        float xB = __expf(lk(elB + er_l) * wB);
        d += xA + xB;
        a.x += xA * fA.x + xB * fB.x;
        a.y += xA * fA.y + xB * fB.y;
        a.z += xA * fA.z + xB * fB.z;
        a.w += xA * fA.w + xB * fB.w;
    }
    if (e < end) {                       // tail edge
        float2 ed = __ldg(&g_edge[e]);
        int   s  = __float_as_int(ed.x);
        float we = ed.y;
        float xs = __expf(lk(__ldg(&g_el[s * 8 + q]) + er_l) * we);
        float4 f = __ldg((const float4*)&g_feat[s * 128 + 4 * lane]);
        d += xs;
        a.x += xs * f.x; a.y += xs * f.y; a.z += xs * f.z; a.w += xs * f.w;
    }

    float inv = (d > 0.f) ? 1.f / d : 0.f;
    *(float4*)&sAcc[warp][4 * lane] =
        make_float4(a.x * inv, a.y * inv, a.z * inv, a.w * inv);
    __syncwarp();

    float4 wA[4], wB[4];
    #pragma unroll
    for (int qq = 0; qq < 4; qq++) {
        wA[qq] = __ldg(&((const float4*)&Wout[lane * 16])[qq]);
        wB[qq] = __ldg(&((const float4*)&Wout[(lane + 32) * 16])[qq]);
    }
    float bias0 = __ldg(&bout[lane]), bias1 = __ldg(&bout[lane + 32]);

    #pragma unroll
    for (int b = 0; b < 2; b++) {
        #pragma unroll
        for (int h = 0; h < 4; h++) {
            const float4* ap = (const float4*)&sAcc[warp][b * 64 + h * 16];
            float acc0 = bias0, acc1 = bias1;
            #pragma unroll
            for (int qq = 0; qq < 4; qq++) {
                float4 av = ap[qq];
                acc0 += av.x * wA[qq].x + av.y * wA[qq].y + av.z * wA[qq].z + av.w * wA[qq].w;
                acc1 += av.x * wB[qq].x + av.y * wB[qq].y + av.z * wB[qq].z + av.w * wB[qq].w;
            }
            float* op = &out[((b * NN + n) * 4 + h) * 64];
            op[lane]      = acc0;
            op[lane + 32] = acc1;
        }
    }
}

// ---------------------------------------------------------------------------
// inputs: vt, x, w, src, dst, W_fc, attn_l, attn_r, W_out, b_out
// ---------------------------------------------------------------------------
extern "C" void kernel_launch(void* const* d_in, const int* in_sizes, int n_in,
                              void* d_out, int out_size) {
    const float* x    = (const float*)d_in[1];
    const float* w    = (const float*)d_in[2];
    const int*   src  = (const int*)  d_in[3];
    const int*   dst  = (const int*)  d_in[4];
    const float* Wfc  = (const float*)d_in[5];
    const float* al   = (const float*)d_in[6];
    const float* ar   = (const float*)d_in[7];
    const float* Wout = (const float*)d_in[8];
    const float* bout = (const float*)d_in[9];
    float* out = (float*)d_out;

    k_featcnt<<<NB / 32, 256>>>(x, Wfc, al, ar, dst);   // 3125 blocks
    k_scan<<<NBLK, SCAN_B>>>();
    k_scatter<<<(EE + 255) / 256, 256>>>(src, dst, w);
    k_agg_out<<<(NN + 7) / 8, 256>>>(Wout, bout, out);
}